// round 1
// baseline (speedup 1.0000x reference)
#include <cuda_runtime.h>
#include <cuda_bf16.h>
#include <cstdint>

// Problem shape constants
#define CO   256
#define CI   2048
#define HW   1024     // 32*32
#define NB   8

// ---------------- device scratch ----------------
__device__ unsigned int   g_amax;                 // bits of max|x| (nonneg float)
__device__ __nv_bfloat16  g_wq[CO * CI];          // integer-valued quantized weights (exact in bf16)
__device__ float          g_scale[CO];            // s_a * s_w[co]
__device__ float          g_bq[CO];               // quantized bias

__device__ __forceinline__ uint32_t smem_u32(const void* p) {
    return static_cast<uint32_t>(__cvta_generic_to_shared(p));
}

// ---------------- kernel 1: reset ----------------
__global__ void init_kernel() { g_amax = 0u; }

// ---------------- kernel 2: abs-max over x ----------------
__global__ void amax_kernel(const float* __restrict__ x, int n4) {
    const float4* x4 = reinterpret_cast<const float4*>(x);
    float m = 0.f;
    for (int i = blockIdx.x * blockDim.x + threadIdx.x; i < n4; i += gridDim.x * blockDim.x) {
        float4 v = x4[i];
        m = fmaxf(m, fmaxf(fmaxf(fabsf(v.x), fabsf(v.y)), fmaxf(fabsf(v.z), fabsf(v.w))));
    }
    #pragma unroll
    for (int o = 16; o; o >>= 1) m = fmaxf(m, __shfl_xor_sync(0xffffffffu, m, o));
    __shared__ float red[8];
    if ((threadIdx.x & 31) == 0) red[threadIdx.x >> 5] = m;
    __syncthreads();
    if (threadIdx.x < 8) {
        m = red[threadIdx.x];
        #pragma unroll
        for (int o = 4; o; o >>= 1) m = fmaxf(m, __shfl_xor_sync(0xffu, m, o));
        if (threadIdx.x == 0) atomicMax(&g_amax, __float_as_uint(m));
    }
}

// ---------------- kernel 3: per-channel weight quant + scales + bias ----------------
__global__ void wprep_kernel(const float* __restrict__ w, const float* __restrict__ bias) {
    const int co  = blockIdx.x;
    const int tid = threadIdx.x;        // 256 threads
    const float* wr = w + (size_t)co * CI;

    float vals[8];
    float m = 0.f;
    #pragma unroll
    for (int j = 0; j < 8; j++) {
        vals[j] = wr[tid + 256 * j];
        m = fmaxf(m, fabsf(vals[j]));
    }
    #pragma unroll
    for (int o = 16; o; o >>= 1) m = fmaxf(m, __shfl_xor_sync(0xffffffffu, m, o));
    __shared__ float red[8];
    __shared__ float s_sw_sh;
    if ((tid & 31) == 0) red[tid >> 5] = m;
    __syncthreads();
    if (tid == 0) {
        float mm = red[0];
        #pragma unroll
        for (int i = 1; i < 8; i++) mm = fmaxf(mm, red[i]);
        float s_w = fmaxf(mm, 1e-8f) / 127.f;
        s_sw_sh = s_w;
        float s_a = fmaxf(__uint_as_float(g_amax), 1e-8f) / 127.f;
        float s_b = s_a * s_w;
        g_scale[co] = s_b;
        g_bq[co]    = rintf(bias[co] / s_b) * s_b;
    }
    __syncthreads();
    const float s_w = s_sw_sh;
    #pragma unroll
    for (int j = 0; j < 8; j++) {
        float q = fminf(fmaxf(rintf(vals[j] / s_w), -128.f), 127.f);
        g_wq[(size_t)co * CI + tid + 256 * j] = __float2bfloat16(q);
    }
}

// ---------------- kernel 4: GEMM (bf16 mma.sync, quantize-x-on-load) ----------------
// out[b, co, hw] = s_a*s_w[co] * sum_ci xi * wi + b_q[co]
#define BM   128
#define BN   128
#define BK   32
#define ASTR 40     // As row stride (bf16 elems), 80B: conflict-free for ldmatrix
#define BSTR 136    // Bs row stride (bf16 elems), 272B

__global__ __launch_bounds__(256, 1) void gemm_kernel(const float* __restrict__ x,
                                                      float* __restrict__ out) {
    __shared__ __align__(16) __nv_bfloat16 As[BM * ASTR];
    __shared__ __align__(16) __nv_bfloat16 Bs[BK * BSTR];

    const int tid  = threadIdx.x;
    const int lane = tid & 31;
    const int warp = tid >> 5;
    const int wm   = warp >> 2;   // 0..1 -> 64 rows each
    const int wn   = warp & 3;    // 0..3 -> 32 cols each

    const int tileM = blockIdx.y;           // 0..1
    const int tileN = blockIdx.x;           // 0..63
    const int b     = tileN >> 3;
    const int hw0   = (tileN & 7) * BN;
    const float* xb = x + (size_t)b * CI * HW + hw0;

    const float s_a    = fmaxf(__uint_as_float(g_amax), 1e-8f) / 127.f;
    const float inv_sa = 1.f / s_a;

    // B-tile (x) global loader coords: 32 k-rows x 128 n-cols, float4
    const int brow = tid >> 5;          // 0..7, +8*i
    const int bcol = (tid & 31) * 4;    // 0..124
    // A-tile (wq) global loader coords: 128 co-rows x 32 k-cols, 8 bf16 chunks
    const int arow = tid >> 2;          // 0..63, +64*i
    const int acol = (tid & 3) * 8;     // 0,8,16,24

    const __nv_bfloat16* wq = g_wq + (size_t)(tileM * BM) * CI;

    float4 bReg[4];
    uint4  aReg[2];

    // prologue: load tile 0
    #pragma unroll
    for (int i = 0; i < 4; i++)
        bReg[i] = *reinterpret_cast<const float4*>(xb + (size_t)(brow + 8 * i) * HW + bcol);
    #pragma unroll
    for (int i = 0; i < 2; i++)
        aReg[i] = *reinterpret_cast<const uint4*>(wq + (size_t)(arow + 64 * i) * CI + acol);

    auto storeTiles = [&]() {
        #pragma unroll
        for (int i = 0; i < 4; i++) {
            float qx = fminf(fmaxf(rintf(bReg[i].x * inv_sa), -128.f), 127.f);
            float qy = fminf(fmaxf(rintf(bReg[i].y * inv_sa), -128.f), 127.f);
            float qz = fminf(fmaxf(rintf(bReg[i].z * inv_sa), -128.f), 127.f);
            float qw = fminf(fmaxf(rintf(bReg[i].w * inv_sa), -128.f), 127.f);
            __nv_bfloat162 p0 = __floats2bfloat162_rn(qx, qy);
            __nv_bfloat162 p1 = __floats2bfloat162_rn(qz, qw);
            __nv_bfloat162* dst =
                reinterpret_cast<__nv_bfloat162*>(&Bs[(brow + 8 * i) * BSTR + bcol]);
            dst[0] = p0;
            dst[1] = p1;
        }
        #pragma unroll
        for (int i = 0; i < 2; i++) {
            uint2* dst = reinterpret_cast<uint2*>(&As[(arow + 64 * i) * ASTR + acol]);
            dst[0] = make_uint2(aReg[i].x, aReg[i].y);
            dst[1] = make_uint2(aReg[i].z, aReg[i].w);
        }
    };
    storeTiles();
    __syncthreads();

    float acc[4][4][4];
    #pragma unroll
    for (int mt = 0; mt < 4; mt++)
        #pragma unroll
        for (int nt = 0; nt < 4; nt++)
            #pragma unroll
            for (int r = 0; r < 4; r++) acc[mt][nt][r] = 0.f;

    const int KT = CI / BK;  // 64
    for (int kt = 0; kt < KT; kt++) {
        if (kt + 1 < KT) {
            const float* xp = xb + (size_t)((kt + 1) * BK) * HW;
            #pragma unroll
            for (int i = 0; i < 4; i++)
                bReg[i] = *reinterpret_cast<const float4*>(xp + (size_t)(brow + 8 * i) * HW + bcol);
            const __nv_bfloat16* wp = wq + (kt + 1) * BK;
            #pragma unroll
            for (int i = 0; i < 2; i++)
                aReg[i] = *reinterpret_cast<const uint4*>(wp + (size_t)(arow + 64 * i) * CI + acol);
        }

        #pragma unroll
        for (int kk = 0; kk < 2; kk++) {
            uint32_t a[4][4];
            #pragma unroll
            for (int mt = 0; mt < 4; mt++) {
                int mr = wm * 64 + mt * 16 + (lane & 15);
                int kc = kk * 16 + (lane >> 4) * 8;
                uint32_t addr = smem_u32(&As[mr * ASTR + kc]);
                asm volatile("ldmatrix.sync.aligned.m8n8.x4.shared.b16 {%0,%1,%2,%3}, [%4];"
                             : "=r"(a[mt][0]), "=r"(a[mt][1]), "=r"(a[mt][2]), "=r"(a[mt][3])
                             : "r"(addr));
            }
            uint32_t bf[2][4];
            #pragma unroll
            for (int np = 0; np < 2; np++) {
                int kr = kk * 16 + (lane & 15);
                int nc = wn * 32 + np * 16 + (lane >> 4) * 8;
                uint32_t addr = smem_u32(&Bs[kr * BSTR + nc]);
                asm volatile("ldmatrix.sync.aligned.m8n8.x4.trans.shared.b16 {%0,%1,%2,%3}, [%4];"
                             : "=r"(bf[np][0]), "=r"(bf[np][1]), "=r"(bf[np][2]), "=r"(bf[np][3])
                             : "r"(addr));
            }
            #pragma unroll
            for (int mt = 0; mt < 4; mt++) {
                #pragma unroll
                for (int nt = 0; nt < 4; nt++) {
                    uint32_t b0 = bf[nt >> 1][(nt & 1) * 2 + 0];
                    uint32_t b1 = bf[nt >> 1][(nt & 1) * 2 + 1];
                    asm volatile(
                        "mma.sync.aligned.m16n8k16.row.col.f32.bf16.bf16.f32 "
                        "{%0,%1,%2,%3}, {%4,%5,%6,%7}, {%8,%9}, {%0,%1,%2,%3};"
                        : "+f"(acc[mt][nt][0]), "+f"(acc[mt][nt][1]),
                          "+f"(acc[mt][nt][2]), "+f"(acc[mt][nt][3])
                        : "r"(a[mt][0]), "r"(a[mt][1]), "r"(a[mt][2]), "r"(a[mt][3]),
                          "r"(b0), "r"(b1));
                }
            }
        }
        __syncthreads();
        if (kt + 1 < KT) storeTiles();
        __syncthreads();
    }

    // epilogue: out = scale[co]*acc + bq[co]
    #pragma unroll
    for (int mt = 0; mt < 4; mt++) {
        int co0 = tileM * BM + wm * 64 + mt * 16 + (lane >> 2);
        float s0 = g_scale[co0],     q0 = g_bq[co0];
        float s1 = g_scale[co0 + 8], q1 = g_bq[co0 + 8];
        #pragma unroll
        for (int nt = 0; nt < 4; nt++) {
            int hw = hw0 + wn * 32 + nt * 8 + (lane & 3) * 2;
            float* o = out + (size_t)b * CO * HW + (size_t)co0 * HW + hw;
            float2 v0 = make_float2(acc[mt][nt][0] * s0 + q0, acc[mt][nt][1] * s0 + q0);
            float2 v1 = make_float2(acc[mt][nt][2] * s1 + q1, acc[mt][nt][3] * s1 + q1);
            *reinterpret_cast<float2*>(o) = v0;
            *reinterpret_cast<float2*>(o + 8 * HW) = v1;
        }
    }
}

// ---------------- launch ----------------
extern "C" void kernel_launch(void* const* d_in, const int* in_sizes, int n_in,
                              void* d_out, int out_size) {
    const float* x    = (const float*)d_in[0];   // [8,2048,32,32]
    const float* w    = (const float*)d_in[1];   // [256,2048,1,1]
    const float* bias = (const float*)d_in[2];   // [256]
    float* out        = (float*)d_out;           // [8,256,32,32]

    init_kernel<<<1, 1>>>();
    const int n4 = (NB * CI * HW) / 4;           // 4,194,304
    amax_kernel<<<1024, 256>>>(x, n4);
    wprep_kernel<<<CO, 256>>>(w, bias);
    dim3 grid(64, 2);
    gemm_kernel<<<grid, 256>>>(x, out);
}

// round 2
// speedup vs baseline: 1.2802x; 1.2802x over previous
#include <cuda_runtime.h>
#include <cuda_bf16.h>
#include <cstdint>

#define CO   256
#define CI   2048
#define HW   1024
#define NB   8

__device__ unsigned int   g_amax;
__device__ __nv_bfloat16  g_wq[CO * CI];
__device__ float          g_scale[CO];
__device__ float          g_bq[CO];

__device__ __forceinline__ uint32_t smem_u32(const void* p) {
    return static_cast<uint32_t>(__cvta_generic_to_shared(p));
}

__global__ void init_kernel() { g_amax = 0u; }

__global__ void amax_kernel(const float* __restrict__ x, int n4) {
    const float4* x4 = reinterpret_cast<const float4*>(x);
    float m = 0.f;
    for (int i = blockIdx.x * blockDim.x + threadIdx.x; i < n4; i += gridDim.x * blockDim.x) {
        float4 v = x4[i];
        m = fmaxf(m, fmaxf(fmaxf(fabsf(v.x), fabsf(v.y)), fmaxf(fabsf(v.z), fabsf(v.w))));
    }
    #pragma unroll
    for (int o = 16; o; o >>= 1) m = fmaxf(m, __shfl_xor_sync(0xffffffffu, m, o));
    __shared__ float red[8];
    if ((threadIdx.x & 31) == 0) red[threadIdx.x >> 5] = m;
    __syncthreads();
    if (threadIdx.x < 8) {
        m = red[threadIdx.x];
        #pragma unroll
        for (int o = 4; o; o >>= 1) m = fmaxf(m, __shfl_xor_sync(0xffu, m, o));
        if (threadIdx.x == 0) atomicMax(&g_amax, __float_as_uint(m));
    }
}

__global__ void wprep_kernel(const float* __restrict__ w, const float* __restrict__ bias) {
    const int co  = blockIdx.x;
    const int tid = threadIdx.x;
    const float* wr = w + (size_t)co * CI;

    float vals[8];
    float m = 0.f;
    #pragma unroll
    for (int j = 0; j < 8; j++) {
        vals[j] = wr[tid + 256 * j];
        m = fmaxf(m, fabsf(vals[j]));
    }
    #pragma unroll
    for (int o = 16; o; o >>= 1) m = fmaxf(m, __shfl_xor_sync(0xffffffffu, m, o));
    __shared__ float red[8];
    __shared__ float s_sw_sh;
    if ((tid & 31) == 0) red[tid >> 5] = m;
    __syncthreads();
    if (tid == 0) {
        float mm = red[0];
        #pragma unroll
        for (int i = 1; i < 8; i++) mm = fmaxf(mm, red[i]);
        float s_w = fmaxf(mm, 1e-8f) / 127.f;
        s_sw_sh = s_w;
        float s_a = fmaxf(__uint_as_float(g_amax), 1e-8f) / 127.f;
        float s_b = s_a * s_w;
        g_scale[co] = s_b;
        g_bq[co]    = rintf(bias[co] / s_b) * s_b;
    }
    __syncthreads();
    const float s_w = s_sw_sh;
    #pragma unroll
    for (int j = 0; j < 8; j++) {
        float q = fminf(fmaxf(rintf(vals[j] / s_w), -128.f), 127.f);
        g_wq[(size_t)co * CI + tid + 256 * j] = __float2bfloat16(q);
    }
}

// ---------------- GEMM: BM=128, BN=64, BK=32, double-buffered ----------------
#define BM   128
#define BN   64
#define BK   32
#define ASTR 40     // A smem row stride (bf16)
#define BSTR 72     // B smem row stride (bf16)

__global__ __launch_bounds__(256, 2) void gemm_kernel(const float* __restrict__ x,
                                                      float* __restrict__ out) {
    __shared__ __align__(16) __nv_bfloat16 As[2][BM * ASTR];
    __shared__ __align__(16) __nv_bfloat16 Bs[2][BK * BSTR];

    const int tid  = threadIdx.x;
    const int lane = tid & 31;
    const int warp = tid >> 5;
    const int wm   = warp >> 1;   // 0..3 -> 32 rows each
    const int wn   = warp & 1;    // 0..1 -> 32 cols each

    const int tileM = blockIdx.x;            // 0..1  (fastest -> L2 x reuse)
    const int tileN = blockIdx.y;            // 0..127
    const int b     = tileN >> 4;
    const int hw0   = (tileN & 15) * BN;
    const float* xb = x + (size_t)b * CI * HW + hw0;

    const float s_a    = fmaxf(__uint_as_float(g_amax), 1e-8f) / 127.f;
    const float inv_sa = 1.f / s_a;

    // B (x) loader: 32 k-rows x 64 n-cols fp32; 2 float4 per thread
    const int brow = tid >> 4;          // 0..15, +16
    const int bcol = (tid & 15) * 4;    // 0..60
    // A (wq) loader via cp.async: 128 rows x 32 cols bf16; 2x16B per thread
    const int arow = tid >> 2;          // 0..63, +64
    const int acol = (tid & 3) * 8;     // 0,8,16,24

    const __nv_bfloat16* wq = g_wq + (size_t)(tileM * BM) * CI;

    float4 bReg[2];

    auto loadB = [&](int kt) {
        const float* xp = xb + (size_t)(kt * BK) * HW;
        bReg[0] = *reinterpret_cast<const float4*>(xp + (size_t)brow * HW + bcol);
        bReg[1] = *reinterpret_cast<const float4*>(xp + (size_t)(brow + 16) * HW + bcol);
    };
    auto storeB = [&](int st) {
        #pragma unroll
        for (int i = 0; i < 2; i++) {
            float qx = fminf(fmaxf(rintf(bReg[i].x * inv_sa), -128.f), 127.f);
            float qy = fminf(fmaxf(rintf(bReg[i].y * inv_sa), -128.f), 127.f);
            float qz = fminf(fmaxf(rintf(bReg[i].z * inv_sa), -128.f), 127.f);
            float qw = fminf(fmaxf(rintf(bReg[i].w * inv_sa), -128.f), 127.f);
            __nv_bfloat162* dst =
                reinterpret_cast<__nv_bfloat162*>(&Bs[st][(brow + 16 * i) * BSTR + bcol]);
            dst[0] = __floats2bfloat162_rn(qx, qy);
            dst[1] = __floats2bfloat162_rn(qz, qw);
        }
    };
    auto loadA = [&](int kt, int st) {
        const __nv_bfloat16* wp = wq + kt * BK;
        #pragma unroll
        for (int i = 0; i < 2; i++) {
            uint32_t dst = smem_u32(&As[st][(arow + 64 * i) * ASTR + acol]);
            const void* src = wp + (size_t)(arow + 64 * i) * CI + acol;
            asm volatile("cp.async.cg.shared.global [%0], [%1], 16;\n" :: "r"(dst), "l"(src));
        }
        asm volatile("cp.async.commit_group;\n");
    };

    // prologue: stage 0
    loadA(0, 0);
    loadB(0);
    storeB(0);
    asm volatile("cp.async.wait_group 0;\n");
    __syncthreads();

    float acc[2][4][4];
    #pragma unroll
    for (int mt = 0; mt < 2; mt++)
        #pragma unroll
        for (int nt = 0; nt < 4; nt++)
            #pragma unroll
            for (int r = 0; r < 4; r++) acc[mt][nt][r] = 0.f;

    const int KT = CI / BK;  // 64
    for (int kt = 0; kt < KT; kt++) {
        const int cur = kt & 1;
        const int nxt = cur ^ 1;
        if (kt + 1 < KT) {
            loadA(kt + 1, nxt);
            loadB(kt + 1);
        }

        #pragma unroll
        for (int kk = 0; kk < 2; kk++) {
            uint32_t a[2][4];
            #pragma unroll
            for (int mt = 0; mt < 2; mt++) {
                int mr = wm * 32 + mt * 16 + (lane & 15);
                int kc = kk * 16 + (lane >> 4) * 8;
                uint32_t addr = smem_u32(&As[cur][mr * ASTR + kc]);
                asm volatile("ldmatrix.sync.aligned.m8n8.x4.shared.b16 {%0,%1,%2,%3}, [%4];"
                             : "=r"(a[mt][0]), "=r"(a[mt][1]), "=r"(a[mt][2]), "=r"(a[mt][3])
                             : "r"(addr));
            }
            uint32_t bf[2][4];
            #pragma unroll
            for (int np = 0; np < 2; np++) {
                int kr = kk * 16 + (lane & 15);
                int nc = wn * 32 + np * 16 + (lane >> 4) * 8;
                uint32_t addr = smem_u32(&Bs[cur][kr * BSTR + nc]);
                asm volatile("ldmatrix.sync.aligned.m8n8.x4.trans.shared.b16 {%0,%1,%2,%3}, [%4];"
                             : "=r"(bf[np][0]), "=r"(bf[np][1]), "=r"(bf[np][2]), "=r"(bf[np][3])
                             : "r"(addr));
            }
            #pragma unroll
            for (int mt = 0; mt < 2; mt++) {
                #pragma unroll
                for (int nt = 0; nt < 4; nt++) {
                    uint32_t b0 = bf[nt >> 1][(nt & 1) * 2 + 0];
                    uint32_t b1 = bf[nt >> 1][(nt & 1) * 2 + 1];
                    asm volatile(
                        "mma.sync.aligned.m16n8k16.row.col.f32.bf16.bf16.f32 "
                        "{%0,%1,%2,%3}, {%4,%5,%6,%7}, {%8,%9}, {%0,%1,%2,%3};"
                        : "+f"(acc[mt][nt][0]), "+f"(acc[mt][nt][1]),
                          "+f"(acc[mt][nt][2]), "+f"(acc[mt][nt][3])
                        : "r"(a[mt][0]), "r"(a[mt][1]), "r"(a[mt][2]), "r"(a[mt][3]),
                          "r"(b0), "r"(b1));
                }
            }
        }

        if (kt + 1 < KT) {
            storeB(nxt);
            asm volatile("cp.async.wait_group 0;\n");
        }
        __syncthreads();
    }

    // epilogue
    #pragma unroll
    for (int mt = 0; mt < 2; mt++) {
        int co0 = tileM * BM + wm * 32 + mt * 16 + (lane >> 2);
        float s0 = g_scale[co0],     q0 = g_bq[co0];
        float s1 = g_scale[co0 + 8], q1 = g_bq[co0 + 8];
        #pragma unroll
        for (int nt = 0; nt < 4; nt++) {
            int hw = hw0 + wn * 32 + nt * 8 + (lane & 3) * 2;
            float* o = out + (size_t)b * CO * HW + (size_t)co0 * HW + hw;
            float2 v0 = make_float2(acc[mt][nt][0] * s0 + q0, acc[mt][nt][1] * s0 + q0);
            float2 v1 = make_float2(acc[mt][nt][2] * s1 + q1, acc[mt][nt][3] * s1 + q1);
            *reinterpret_cast<float2*>(o) = v0;
            *reinterpret_cast<float2*>(o + 8 * HW) = v1;
        }
    }
}

extern "C" void kernel_launch(void* const* d_in, const int* in_sizes, int n_in,
                              void* d_out, int out_size) {
    const float* x    = (const float*)d_in[0];
    const float* w    = (const float*)d_in[1];
    const float* bias = (const float*)d_in[2];
    float* out        = (float*)d_out;

    init_kernel<<<1, 1>>>();
    const int n4 = (NB * CI * HW) / 4;
    amax_kernel<<<1024, 256>>>(x, n4);
    wprep_kernel<<<CO, 256>>>(w, bias);
    dim3 grid(2, 128);
    gemm_kernel<<<grid, 256>>>(x, out);
}